// round 1
// baseline (speedup 1.0000x reference)
#include <cuda_runtime.h>
#include <math.h>

#define Vv  32000
#define Ee  512
#define Hh  512
#define Bb  16
#define Ss  128
#define G4  2048   // 4*H
#define MBr 2048   // S*B rows

// ---------------- scratch (static device memory; no allocation) ----------------
__device__ float g_x0[(size_t)MBr * Ee];        // layer0 input  [s*B+b][512]
__device__ float g_x1[(size_t)MBr * 1024];      // layer1 input  [s*B+b][1024]
__device__ float g_xg[2][(size_t)MBr * G4];     // per-dir gate preacts [row][2048]
__device__ float g_h[2][2][Bb * Hh];            // [parity][dir][b*H]
__device__ float g_c[2][Bb * Hh];               // [dir][b*H]
__device__ float g_hfin[(size_t)Bb * Ss * 1024];// layer1 output [b][s][1024]

// ---------------- embedding gather ----------------
__global__ void embed_kernel(const int* __restrict__ tok, const float* __restrict__ ew) {
    int sb = blockIdx.x;            // s*B + b
    int s = sb >> 4, b = sb & 15;
    int t = tok[b * Ss + s];
    const float4* src = reinterpret_cast<const float4*>(ew + (size_t)t * Ee);
    float4* dst = reinterpret_cast<float4*>(g_x0 + (size_t)sb * Ee);
    dst[threadIdx.x] = src[threadIdx.x];   // 128 threads x float4 = 512 floats
}

// ---------------- zero h/c state (both parities, both dirs) ----------------
__global__ void zero_state() {
    int i = blockIdx.x * blockDim.x + threadIdx.x;
    if (i < 2 * 2 * Bb * Hh) (&g_h[0][0][0])[i] = 0.f;
    if (i < 2 * Bb * Hh)     (&g_c[0][0])[i]    = 0.f;
}

// ---------------- generic fp32 GEMM:  C = A[M,K] * Bw[N,K]^T + bias ----------------
// mode 0: C[row*N+col] = acc + b1[col] + b2[col]              (xg precompute)
// mode 1: C[(b*N+col)*S + s] = acc + b1[col], row = b*S+s     (final, writes [B,V,S])
__global__ __launch_bounds__(256) void gemm_nt(
    const float* __restrict__ A, const float* __restrict__ Bw,
    const float* __restrict__ b1, const float* __restrict__ b2,
    float* __restrict__ C, int M, int N, int K, int mode)
{
    __shared__ float As[8][128];
    __shared__ float Bs[8][128];
    int tid = threadIdx.x;
    int m0 = blockIdx.y << 7, n0 = blockIdx.x << 7;
    int tx = tid & 15, ty = tid >> 4;
    int lr = tid >> 1;              // 0..127 (row of the tile this thread loads)
    int lk = (tid & 1) << 2;        // 0 or 4
    const float* Ap = A  + (size_t)(m0 + lr) * K + lk;
    const float* Bp = Bw + (size_t)(n0 + lr) * K + lk;

    float acc[8][8];
#pragma unroll
    for (int i = 0; i < 8; i++)
#pragma unroll
        for (int j = 0; j < 8; j++) acc[i][j] = 0.f;

    for (int k0 = 0; k0 < K; k0 += 8) {
        float4 av = *reinterpret_cast<const float4*>(Ap + k0);
        float4 bv = *reinterpret_cast<const float4*>(Bp + k0);
        As[lk + 0][lr] = av.x; As[lk + 1][lr] = av.y;
        As[lk + 2][lr] = av.z; As[lk + 3][lr] = av.w;
        Bs[lk + 0][lr] = bv.x; Bs[lk + 1][lr] = bv.y;
        Bs[lk + 2][lr] = bv.z; Bs[lk + 3][lr] = bv.w;
        __syncthreads();
#pragma unroll
        for (int kk = 0; kk < 8; kk++) {
            float a[8], b[8];
            *reinterpret_cast<float4*>(a)     = *reinterpret_cast<const float4*>(&As[kk][ty << 2]);
            *reinterpret_cast<float4*>(a + 4) = *reinterpret_cast<const float4*>(&As[kk][64 + (ty << 2)]);
            *reinterpret_cast<float4*>(b)     = *reinterpret_cast<const float4*>(&Bs[kk][tx << 2]);
            *reinterpret_cast<float4*>(b + 4) = *reinterpret_cast<const float4*>(&Bs[kk][64 + (tx << 2)]);
#pragma unroll
            for (int i = 0; i < 8; i++)
#pragma unroll
                for (int j = 0; j < 8; j++)
                    acc[i][j] = fmaf(a[i], b[j], acc[i][j]);
        }
        __syncthreads();
    }

#pragma unroll
    for (int i = 0; i < 8; i++) {
        int row = m0 + (ty << 2) + (i & 3) + ((i >> 2) << 6);
#pragma unroll
        for (int j = 0; j < 8; j++) {
            int col = n0 + (tx << 2) + (j & 3) + ((j >> 2) << 6);
            float v = acc[i][j] + b1[col];
            if (b2) v += b2[col];
            if (mode == 0) {
                C[(size_t)row * N + col] = v;
            } else {
                int bb = row >> 7, ss = row & 127;
                C[((size_t)bb * N + col) * Ss + ss] = v;
            }
        }
    }
}

// ---------------- one LSTM timestep, both directions ----------------
// grid (64, 2): blockIdx.x = 8-unit chunk, blockIdx.y = dir. 128 threads.
// Block computes z = h_prev @ Whh^T for its 32 gate rows (4 gates x 8 units),
// all 16 batches, then applies gates and writes h (state + layer output).
__global__ __launch_bounds__(128) void lstm_step(
    const float* __restrict__ Whh_f, const float* __restrict__ Whh_b,
    int mode, int t)
{
    __shared__ float hs[Bb * Hh];   // 32 KB: h_prev [b][k]
    __shared__ float ws[32 * 128];  // 16 KB: Whh chunk [32 rows][128 k]; reused as zr
    int dir = blockIdx.y;
    int u0 = blockIdx.x << 3;
    int tid = threadIdx.x;
    int rg = tid >> 4, ks = tid & 15;       // row-group (4 rows), k-split lane
    int tidx = dir ? (Ss - 1 - t) : t;
    const float* Whh = dir ? Whh_b : Whh_f;
    const float* hprev = g_h[t & 1][dir];

    {   // cooperative load of full h_prev (16x512)
        float4* d4 = reinterpret_cast<float4*>(hs);
        const float4* s4 = reinterpret_cast<const float4*>(hprev);
#pragma unroll
        for (int i = 0; i < 16; i++) d4[i * 128 + tid] = s4[i * 128 + tid];
    }

    float acc[4][16];
#pragma unroll
    for (int r = 0; r < 4; r++)
#pragma unroll
        for (int b = 0; b < 16; b++) acc[r][b] = 0.f;

#pragma unroll 1
    for (int kc = 0; kc < 4; kc++) {
        __syncthreads();
        {   // stage Whh rows [32][kc*128 .. +128)
            float4* d4 = reinterpret_cast<float4*>(ws);
#pragma unroll
            for (int i = 0; i < 8; i++) {
                int f4 = i * 128 + tid;
                int lrr = f4 >> 5;                       // local row 0..31
                int c4 = f4 & 31;
                int R = (lrr >> 3) * Hh + u0 + (lrr & 7); // gate*512 + unit
                d4[f4] = *reinterpret_cast<const float4*>(
                    Whh + (size_t)R * Hh + (kc << 7) + (c4 << 2));
            }
        }
        __syncthreads();
#pragma unroll
        for (int j = 0; j < 8; j++) {
            int k = (j << 4) + ks;
            const float* wrow = ws + ((rg << 2) * 128) + k;
            float w0 = wrow[0];
            float w1 = wrow[128];
            float w2 = wrow[256];
            float w3 = wrow[384];
            int kg = (kc << 7) + k;
#pragma unroll
            for (int b = 0; b < 16; b++) {
                float hv = hs[(b << 9) + kg];            // broadcast-friendly
                acc[0][b] = fmaf(w0, hv, acc[0][b]);
                acc[1][b] = fmaf(w1, hv, acc[1][b]);
                acc[2][b] = fmaf(w2, hv, acc[2][b]);
                acc[3][b] = fmaf(w3, hv, acc[3][b]);
            }
        }
    }

    // reduce over the 16 k-split lanes (within each half-warp)
#pragma unroll
    for (int off = 8; off >= 1; off >>= 1)
#pragma unroll
        for (int r = 0; r < 4; r++)
#pragma unroll
            for (int b = 0; b < 16; b++)
                acc[r][b] += __shfl_xor_sync(0xffffffffu, acc[r][b], off);

    __syncthreads();                 // done reading ws -> safe to alias
    float* zr = ws;                  // [32 local rows][16 b]
    if (ks == 0) {
#pragma unroll
        for (int r = 0; r < 4; r++)
#pragma unroll
            for (int b = 0; b < 16; b++)
                zr[((rg << 2) + r) * 16 + b] = acc[r][b];
    }
    __syncthreads();

    {   // gates: 128 threads <-> 16 b x 8 units
        int b = tid >> 3, ui = tid & 7;
        int unit = u0 + ui;
        const float* xgd = g_xg[dir] + (size_t)(tidx * Bb + b) * G4 + unit;
        float zi = zr[(ui) * 16 + b]      + xgd[0];
        float zf = zr[(8 + ui) * 16 + b]  + xgd[Hh];
        float zg = zr[(16 + ui) * 16 + b] + xgd[2 * Hh];
        float zo = zr[(24 + ui) * 16 + b] + xgd[3 * Hh];
        int ci = b * Hh + unit;
        float c = g_c[dir][ci];
        float ig = 1.f / (1.f + expf(-zi));
        float fg = 1.f / (1.f + expf(-zf));
        float gg = tanhf(zg);
        float og = 1.f / (1.f + expf(-zo));
        c = fg * c + ig * gg;
        float h = og * tanhf(c);
        g_c[dir][ci] = c;
        g_h[(t & 1) ^ 1][dir][ci] = h;
        if (mode == 0)
            g_x1[(size_t)(tidx * Bb + b) * 1024 + (dir << 9) + unit] = h;
        else
            g_hfin[(size_t)b * (Ss * 1024) + tidx * 1024 + (dir << 9) + unit] = h;
    }
}

// ---------------- launch ----------------
extern "C" void kernel_launch(void* const* d_in, const int* in_sizes, int n_in,
                              void* d_out, int out_size)
{
    const int*   tok  = (const int*)d_in[0];
    const float* ew   = (const float*)d_in[1];
    const float* Wih0f = (const float*)d_in[2],  *Whh0f = (const float*)d_in[3];
    const float* bih0f = (const float*)d_in[4],  *bhh0f = (const float*)d_in[5];
    const float* Wih0b = (const float*)d_in[6],  *Whh0b = (const float*)d_in[7];
    const float* bih0b = (const float*)d_in[8],  *bhh0b = (const float*)d_in[9];
    const float* Wih1f = (const float*)d_in[10], *Whh1f = (const float*)d_in[11];
    const float* bih1f = (const float*)d_in[12], *bhh1f = (const float*)d_in[13];
    const float* Wih1b = (const float*)d_in[14], *Whh1b = (const float*)d_in[15];
    const float* bih1b = (const float*)d_in[16], *bhh1b = (const float*)d_in[17];
    const float* linw = (const float*)d_in[18],  *linb  = (const float*)d_in[19];
    float* out = (float*)d_out;

    float *px0, *px1, *pxg, *phf;
    cudaGetSymbolAddress((void**)&px0, g_x0);
    cudaGetSymbolAddress((void**)&px1, g_x1);
    cudaGetSymbolAddress((void**)&pxg, g_xg);
    cudaGetSymbolAddress((void**)&phf, g_hfin);
    float* pxg0 = pxg;
    float* pxg1 = pxg + (size_t)MBr * G4;

    embed_kernel<<<MBr, 128>>>(tok, ew);

    // ---- layer 0 ----
    gemm_nt<<<dim3(G4 / 128, MBr / 128), 256>>>(px0, Wih0f, bih0f, bhh0f, pxg0, MBr, G4, Ee, 0);
    gemm_nt<<<dim3(G4 / 128, MBr / 128), 256>>>(px0, Wih0b, bih0b, bhh0b, pxg1, MBr, G4, Ee, 0);
    zero_state<<<128, 256>>>();
    for (int t = 0; t < Ss; t++)
        lstm_step<<<dim3(64, 2), 128>>>(Whh0f, Whh0b, 0, t);

    // ---- layer 1 ----
    gemm_nt<<<dim3(G4 / 128, MBr / 128), 256>>>(px1, Wih1f, bih1f, bhh1f, pxg0, MBr, G4, 1024, 0);
    gemm_nt<<<dim3(G4 / 128, MBr / 128), 256>>>(px1, Wih1b, bih1b, bhh1b, pxg1, MBr, G4, 1024, 0);
    zero_state<<<128, 256>>>();
    for (int t = 0; t < Ss; t++)
        lstm_step<<<dim3(64, 2), 128>>>(Whh1f, Whh1b, 1, t);

    // ---- final projection: [B*S,1024] x [V,1024]^T -> out[B,V,S] ----
    gemm_nt<<<dim3(Vv / 128, MBr / 128), 256>>>(phf, linw, linb, nullptr, out, MBr, Vv, 1024, 1);
}

// round 3
// speedup vs baseline: 1.6376x; 1.6376x over previous
#include <cuda_runtime.h>
#include <math.h>
#include <stdint.h>

#define Vv  32000
#define Ee  512
#define Hh  512
#define Bb  16
#define Ss  128
#define G4  2048   // 4*H
#define MBr 2048   // S*B rows

// ---------------- scratch (static device memory; no allocation) ----------------
__device__ float g_x0[(size_t)MBr * Ee];        // layer0 input  [s*B+b][512]
__device__ float g_x1[(size_t)MBr * 1024];      // layer1 input  [s*B+b][1024]
__device__ float g_xg[2][(size_t)MBr * G4];     // per-dir gate preacts [row][2048]
__device__ float g_h[2][2][Bb * Hh];            // [parity][dir][b*H]
__device__ float g_c[2][Bb * Hh];               // [dir][b*H]
__device__ float g_hfin[(size_t)Bb * Ss * 1024];// layer1 output [b][s][1024] (tf32-rounded)
__device__ float g_wt[(size_t)Vv * 1024];       // lin_w tf32-rounded

// ================= helpers =================
__device__ __forceinline__ uint32_t smem_u32(const void* p) {
    uint32_t a;
    asm("{ .reg .u64 t; cvta.to.shared.u64 t, %1; cvt.u32.u64 %0, t; }" : "=r"(a) : "l"(p));
    return a;
}
__device__ __forceinline__ void cp16(uint32_t dst, const void* src) {
    asm volatile("cp.async.cg.shared.global [%0], [%1], 16;" :: "r"(dst), "l"(src) : "memory");
}
__device__ __forceinline__ float rna_tf32(float x) {
    uint32_t u;
    asm("cvt.rna.tf32.f32 %0, %1;" : "=r"(u) : "f"(x));
    return __uint_as_float(u);
}
__device__ __forceinline__ void mma_tf32_16x8x8(float* c, const uint32_t* a, const uint32_t* b) {
    asm volatile(
        "mma.sync.aligned.m16n8k8.row.col.f32.tf32.tf32.f32 "
        "{%0,%1,%2,%3}, {%4,%5,%6,%7}, {%8,%9}, {%0,%1,%2,%3};\n"
        : "+f"(c[0]), "+f"(c[1]), "+f"(c[2]), "+f"(c[3])
        : "r"(a[0]), "r"(a[1]), "r"(a[2]), "r"(a[3]), "r"(b[0]), "r"(b[1]));
}

// ================= tf32 mma.sync GEMM (final projection) =================
// D[2048, 32000] = A[2048,1024] * Bw[32000,1024]^T + bias, scatter to out[B,V,S]
// CTA tile 128x128, 4 warps (2x2) each 64x64, BK=16, 3-stage cp.async pipeline.
#define KSTR 20                 // smem row stride in floats (conflict-free)
#define STGF (2 * 128 * KSTR)   // floats per stage (A + B)
#define STGB (STGF * 4)         // 20480 bytes
#define GEMM_DSM 67584          // max(3*STGB=61440, 128*132*4=67584)

__global__ __launch_bounds__(128) void gemm_mma_final(
    const float* __restrict__ A, const float* __restrict__ Bw,
    const float* __restrict__ bias, float* __restrict__ out)
{
    extern __shared__ float dsm[];
    int tid = threadIdx.x, wid = tid >> 5, lane = tid & 31;
    int warp_m = wid & 1, warp_n = wid >> 1;
    int gr = lane >> 2, gc = lane & 3;
    int m0 = blockIdx.x << 7;       // x = M-tile (16) -> wave reuses B tiles in L2
    int n0 = blockIdx.y << 7;
    uint32_t base = smem_u32(dsm);

    const float* Ag = A + (size_t)m0 * 1024;
    const float* Bg = Bw + (size_t)n0 * 1024;

    float acc[4][8][4];
#pragma unroll
    for (int mi = 0; mi < 4; mi++)
#pragma unroll
        for (int ni = 0; ni < 8; ni++)
#pragma unroll
            for (int q = 0; q < 4; q++) acc[mi][ni][q] = 0.f;

#define LOAD_STAGE(s, c) do {                                               \
        uint32_t sb_ = base + (s) * STGB;                                   \
        const float* Ac_ = Ag + (c) * 16;                                   \
        const float* Bc_ = Bg + (c) * 16;                                   \
        _Pragma("unroll")                                                   \
        for (int q_ = 0; q_ < 4; q_++) {                                    \
            int f_ = q_ * 128 + tid;                                        \
            int row_ = f_ >> 2, k4_ = f_ & 3;                               \
            cp16(sb_ + row_ * (KSTR * 4) + k4_ * 16,                        \
                 Ac_ + (size_t)row_ * 1024 + k4_ * 4);                      \
            cp16(sb_ + 128 * (KSTR * 4) + row_ * (KSTR * 4) + k4_ * 16,    \
                 Bc_ + (size_t)row_ * 1024 + k4_ * 4);                      \
        }                                                                   \
        asm volatile("cp.async.commit_group;" ::: "memory");                \
    } while (0)

    LOAD_STAGE(0, 0);
    LOAD_STAGE(1, 1);
    LOAD_STAGE(2, 2);

    int s = 0;
    for (int c = 0; c < 64; c++) {
        asm volatile("cp.async.wait_group 2;" ::: "memory");
        __syncthreads();
        const float* As = dsm + s * STGF;
        const float* Bs = As + 128 * KSTR;
#pragma unroll
        for (int kk = 0; kk < 16; kk += 8) {
            uint32_t af[4][4], bf[8][2];
#pragma unroll
            for (int mi = 0; mi < 4; mi++) {
                int r = warp_m * 64 + mi * 16 + gr;
                const float* p = As + r * KSTR + kk + gc;
                af[mi][0] = __float_as_uint(p[0]);
                af[mi][1] = __float_as_uint(p[8 * KSTR]);
                af[mi][2] = __float_as_uint(p[4]);
                af[mi][3] = __float_as_uint(p[8 * KSTR + 4]);
            }
#pragma unroll
            for (int ni = 0; ni < 8; ni++) {
                int n = warp_n * 64 + ni * 8 + gr;
                const float* p = Bs + n * KSTR + kk + gc;
                bf[ni][0] = __float_as_uint(p[0]);
                bf[ni][1] = __float_as_uint(p[4]);
            }
#pragma unroll
            for (int mi = 0; mi < 4; mi++)
#pragma unroll
                for (int ni = 0; ni < 8; ni++)
                    mma_tf32_16x8x8(acc[mi][ni], af[mi], bf[ni]);
        }
        __syncthreads();
        if (c < 61) LOAD_STAGE(s, c + 3);
        else asm volatile("cp.async.commit_group;" ::: "memory");
        s++; if (s == 3) s = 0;
    }
    asm volatile("cp.async.wait_group 0;" ::: "memory");
    __syncthreads();

    // ---- epilogue: stage [n][m] in smem, then coalesced float4 stores ----
    float* es = dsm;  // 128 x (stride 132)
#pragma unroll
    for (int mi = 0; mi < 4; mi++) {
        int row = warp_m * 64 + mi * 16 + gr;
#pragma unroll
        for (int ni = 0; ni < 8; ni++) {
            int col = warp_n * 64 + ni * 8 + gc * 2;
            es[col * 132 + row]           = acc[mi][ni][0];
            es[(col + 1) * 132 + row]     = acc[mi][ni][1];
            es[col * 132 + row + 8]       = acc[mi][ni][2];
            es[(col + 1) * 132 + row + 8] = acc[mi][ni][3];
        }
    }
    __syncthreads();
    int bb = blockIdx.x;                       // 128 rows == one batch block
    float* ob = out + (size_t)bb * Vv * Ss;
#pragma unroll 4
    for (int i = 0; i < 32; i++) {
        int f4 = i * 128 + tid;
        int rown = f4 >> 5;                    // 0..127 (one row per warp-iter)
        int c4 = f4 & 31;
        float4 v = *reinterpret_cast<const float4*>(es + rown * 132 + c4 * 4);
        float bv = bias[n0 + rown];
        v.x += bv; v.y += bv; v.z += bv; v.w += bv;
        *reinterpret_cast<float4*>(ob + (size_t)(n0 + rown) * Ss + c4 * 4) = v;
    }
#undef LOAD_STAGE
}

// ---------------- rna tf32 rounding pass (lin_w -> g_wt) ----------------
__global__ void rna_round_kernel(const float* __restrict__ in, float* __restrict__ out) {
    int i = blockIdx.x * blockDim.x + threadIdx.x;
    float4 v = reinterpret_cast<const float4*>(in)[i];
    v.x = rna_tf32(v.x); v.y = rna_tf32(v.y); v.z = rna_tf32(v.z); v.w = rna_tf32(v.w);
    reinterpret_cast<float4*>(out)[i] = v;
}

// ---------------- embedding gather ----------------
__global__ void embed_kernel(const int* __restrict__ tok, const float* __restrict__ ew) {
    int sb = blockIdx.x;            // s*B + b
    int s = sb >> 4, b = sb & 15;
    int t = tok[b * Ss + s];
    const float4* src = reinterpret_cast<const float4*>(ew + (size_t)t * Ee);
    float4* dst = reinterpret_cast<float4*>(g_x0 + (size_t)sb * Ee);
    dst[threadIdx.x] = src[threadIdx.x];
}

// ---------------- zero h/c state ----------------
__global__ void zero_state() {
    int i = blockIdx.x * blockDim.x + threadIdx.x;
    if (i < 2 * 2 * Bb * Hh) (&g_h[0][0][0])[i] = 0.f;
    if (i < 2 * Bb * Hh)     (&g_c[0][0])[i]    = 0.f;
}

// ---------------- fp32 SIMT GEMM for xg precompute ----------------
__global__ __launch_bounds__(256) void gemm_nt(
    const float* __restrict__ A, const float* __restrict__ Bw,
    const float* __restrict__ b1, const float* __restrict__ b2,
    float* __restrict__ C, int M, int N, int K)
{
    __shared__ float As[8][128];
    __shared__ float Bs[8][128];
    int tid = threadIdx.x;
    int m0 = blockIdx.y << 7, n0 = blockIdx.x << 7;
    int tx = tid & 15, ty = tid >> 4;
    int lr = tid >> 1;
    int lk = (tid & 1) << 2;
    const float* Ap = A  + (size_t)(m0 + lr) * K + lk;
    const float* Bp = Bw + (size_t)(n0 + lr) * K + lk;

    float acc[8][8];
#pragma unroll
    for (int i = 0; i < 8; i++)
#pragma unroll
        for (int j = 0; j < 8; j++) acc[i][j] = 0.f;

    for (int k0 = 0; k0 < K; k0 += 8) {
        float4 av = *reinterpret_cast<const float4*>(Ap + k0);
        float4 bv = *reinterpret_cast<const float4*>(Bp + k0);
        As[lk + 0][lr] = av.x; As[lk + 1][lr] = av.y;
        As[lk + 2][lr] = av.z; As[lk + 3][lr] = av.w;
        Bs[lk + 0][lr] = bv.x; Bs[lk + 1][lr] = bv.y;
        Bs[lk + 2][lr] = bv.z; Bs[lk + 3][lr] = bv.w;
        __syncthreads();
#pragma unroll
        for (int kk = 0; kk < 8; kk++) {
            float a[8], b[8];
            *reinterpret_cast<float4*>(a)     = *reinterpret_cast<const float4*>(&As[kk][ty << 2]);
            *reinterpret_cast<float4*>(a + 4) = *reinterpret_cast<const float4*>(&As[kk][64 + (ty << 2)]);
            *reinterpret_cast<float4*>(b)     = *reinterpret_cast<const float4*>(&Bs[kk][tx << 2]);
            *reinterpret_cast<float4*>(b + 4) = *reinterpret_cast<const float4*>(&Bs[kk][64 + (tx << 2)]);
#pragma unroll
            for (int i = 0; i < 8; i++)
#pragma unroll
                for (int j = 0; j < 8; j++)
                    acc[i][j] = fmaf(a[i], b[j], acc[i][j]);
        }
        __syncthreads();
    }

#pragma unroll
    for (int i = 0; i < 8; i++) {
        int row = m0 + (ty << 2) + (i & 3) + ((i >> 2) << 6);
#pragma unroll
        for (int j = 0; j < 8; j++) {
            int col = n0 + (tx << 2) + (j & 3) + ((j >> 2) << 6);
            C[(size_t)row * N + col] = acc[i][j] + b1[col] + b2[col];
        }
    }
}

// ---------------- one LSTM timestep, both directions ----------------
__global__ __launch_bounds__(128) void lstm_step(
    const float* __restrict__ Whh_f, const float* __restrict__ Whh_b,
    int mode, int t)
{
    __shared__ float hs[Bb * Hh];   // 32 KB
    __shared__ float ws[32 * 128];  // 16 KB (reused as zr)
    int dir = blockIdx.y;
    int u0 = blockIdx.x << 3;
    int tid = threadIdx.x;
    int rg = tid >> 4, ks = tid & 15;
    int tidx = dir ? (Ss - 1 - t) : t;
    const float* Whh = dir ? Whh_b : Whh_f;
    const float* hprev = g_h[t & 1][dir];

    {
        float4* d4 = reinterpret_cast<float4*>(hs);
        const float4* s4 = reinterpret_cast<const float4*>(hprev);
#pragma unroll
        for (int i = 0; i < 16; i++) d4[i * 128 + tid] = s4[i * 128 + tid];
    }

    float acc[4][16];
#pragma unroll
    for (int r = 0; r < 4; r++)
#pragma unroll
        for (int b = 0; b < 16; b++) acc[r][b] = 0.f;

#pragma unroll 1
    for (int kc = 0; kc < 4; kc++) {
        __syncthreads();
        {
            float4* d4 = reinterpret_cast<float4*>(ws);
#pragma unroll
            for (int i = 0; i < 8; i++) {
                int f4 = i * 128 + tid;
                int lrr = f4 >> 5;
                int c4 = f4 & 31;
                int R = (lrr >> 3) * Hh + u0 + (lrr & 7);
                d4[f4] = *reinterpret_cast<const float4*>(
                    Whh + (size_t)R * Hh + (kc << 7) + (c4 << 2));
            }
        }
        __syncthreads();
#pragma unroll
        for (int j = 0; j < 8; j++) {
            int k = (j << 4) + ks;
            const float* wrow = ws + ((rg << 2) * 128) + k;
            float w0 = wrow[0];
            float w1 = wrow[128];
            float w2 = wrow[256];
            float w3 = wrow[384];
            int kg = (kc << 7) + k;
#pragma unroll
            for (int b = 0; b < 16; b++) {
                float hv = hs[(b << 9) + kg];
                acc[0][b] = fmaf(w0, hv, acc[0][b]);
                acc[1][b] = fmaf(w1, hv, acc[1][b]);
                acc[2][b] = fmaf(w2, hv, acc[2][b]);
                acc[3][b] = fmaf(w3, hv, acc[3][b]);
            }
        }
    }

#pragma unroll
    for (int off = 8; off >= 1; off >>= 1)
#pragma unroll
        for (int r = 0; r < 4; r++)
#pragma unroll
            for (int b = 0; b < 16; b++)
                acc[r][b] += __shfl_xor_sync(0xffffffffu, acc[r][b], off);

    __syncthreads();
    float* zr = ws;
    if (ks == 0) {
#pragma unroll
        for (int r = 0; r < 4; r++)
#pragma unroll
            for (int b = 0; b < 16; b++)
                zr[((rg << 2) + r) * 16 + b] = acc[r][b];
    }
    __syncthreads();

    {
        int b = tid >> 3, ui = tid & 7;
        int unit = u0 + ui;
        const float* xgd = g_xg[dir] + (size_t)(tidx * Bb + b) * G4 + unit;
        float zi = zr[(ui) * 16 + b]      + xgd[0];
        float zf = zr[(8 + ui) * 16 + b]  + xgd[Hh];
        float zg = zr[(16 + ui) * 16 + b] + xgd[2 * Hh];
        float zo = zr[(24 + ui) * 16 + b] + xgd[3 * Hh];
        int ci = b * Hh + unit;
        float c = g_c[dir][ci];
        float ig = 1.f / (1.f + expf(-zi));
        float fg = 1.f / (1.f + expf(-zf));
        float gg = tanhf(zg);
        float og = 1.f / (1.f + expf(-zo));
        c = fg * c + ig * gg;
        float h = og * tanhf(c);
        g_c[dir][ci] = c;
        g_h[(t & 1) ^ 1][dir][ci] = h;
        if (mode == 0)
            g_x1[(size_t)(tidx * Bb + b) * 1024 + (dir << 9) + unit] = h;
        else
            g_hfin[(size_t)b * (Ss * 1024) + tidx * 1024 + (dir << 9) + unit] = rna_tf32(h);
    }
}

// ---------------- launch ----------------
extern "C" void kernel_launch(void* const* d_in, const int* in_sizes, int n_in,
                              void* d_out, int out_size)
{
    const int*   tok  = (const int*)d_in[0];
    const float* ew   = (const float*)d_in[1];
    const float* Wih0f = (const float*)d_in[2],  *Whh0f = (const float*)d_in[3];
    const float* bih0f = (const float*)d_in[4],  *bhh0f = (const float*)d_in[5];
    const float* Wih0b = (const float*)d_in[6],  *Whh0b = (const float*)d_in[7];
    const float* bih0b = (const float*)d_in[8],  *bhh0b = (const float*)d_in[9];
    const float* Wih1f = (const float*)d_in[10], *Whh1f = (const float*)d_in[11];
    const float* bih1f = (const float*)d_in[12], *bhh1f = (const float*)d_in[13];
    const float* Wih1b = (const float*)d_in[14], *Whh1b = (const float*)d_in[15];
    const float* bih1b = (const float*)d_in[16], *bhh1b = (const float*)d_in[17];
    const float* linw = (const float*)d_in[18],  *linb  = (const float*)d_in[19];
    float* out = (float*)d_out;

    float *px0, *px1, *pxg, *phf, *pwt;
    cudaGetSymbolAddress((void**)&px0, g_x0);
    cudaGetSymbolAddress((void**)&px1, g_x1);
    cudaGetSymbolAddress((void**)&pxg, g_xg);
    cudaGetSymbolAddress((void**)&phf, g_hfin);
    cudaGetSymbolAddress((void**)&pwt, g_wt);
    float* pxg0 = pxg;
    float* pxg1 = pxg + (size_t)MBr * G4;

    cudaFuncSetAttribute(gemm_mma_final, cudaFuncAttributeMaxDynamicSharedMemorySize, GEMM_DSM);

    embed_kernel<<<MBr, 128>>>(tok, ew);
    rna_round_kernel<<<(Vv * 1024 / 4) / 256, 256>>>(linw, pwt);

    // ---- layer 0 ----
    gemm_nt<<<dim3(G4 / 128, MBr / 128), 256>>>(px0, Wih0f, bih0f, bhh0f, pxg0, MBr, G4, Ee);
    gemm_nt<<<dim3(G4 / 128, MBr / 128), 256>>>(px0, Wih0b, bih0b, bhh0b, pxg1, MBr, G4, Ee);
    zero_state<<<128, 256>>>();
    for (int t = 0; t < Ss; t++)
        lstm_step<<<dim3(64, 2), 128>>>(Whh0f, Whh0b, 0, t);

    // ---- layer 1 ----
    gemm_nt<<<dim3(G4 / 128, MBr / 128), 256>>>(px1, Wih1f, bih1f, bhh1f, pxg0, MBr, G4, 1024);
    gemm_nt<<<dim3(G4 / 128, MBr / 128), 256>>>(px1, Wih1b, bih1b, bhh1b, pxg1, MBr, G4, 1024);
    zero_state<<<128, 256>>>();
    for (int t = 0; t < Ss; t++)
        lstm_step<<<dim3(64, 2), 128>>>(Whh1f, Whh1b, 1, t);

    // ---- final projection: tf32 mma.sync [2048,1024] x [32000,1024]^T -> out[B,V,S] ----
    gemm_mma_final<<<dim3(MBr / 128, Vv / 128), 128, GEMM_DSM>>>(phf, pwt, linb, out);
}

// round 5
// speedup vs baseline: 2.0915x; 1.2771x over previous
#include <cuda_runtime.h>
#include <math.h>
#include <stdint.h>

#define Vv  32000
#define Ee  512
#define Hh  512
#define Bb  16
#define Ss  128
#define G4  2048   // 4*H
#define MBr 2048   // S*B rows

// ---------------- scratch (static device memory; no allocation) ----------------
__device__ float g_x0[(size_t)MBr * Ee];        // layer0 input (tf32-rounded)
__device__ float g_x1[(size_t)MBr * 1024];      // layer1 input (tf32-rounded)
__device__ float g_xg[2][(size_t)MBr * G4];     // per-dir gate preacts
__device__ float g_h[2][2][Bb * Hh];            // [parity][dir][b*H]
__device__ float g_hfin[(size_t)Bb * Ss * 1024];// layer1 output (tf32-rounded)
__device__ float g_wt[(size_t)Vv * 1024];       // lin_w tf32-rounded
__device__ float g_wpack[(size_t)4096 * 1024];  // packed+rounded Wih (both dirs)
__device__ float g_bias[4096];                  // combined bih+bhh (both dirs)
__device__ unsigned g_bar_cnt[2];
__device__ unsigned g_bar_gen[2];

// ================= helpers =================
__device__ __forceinline__ uint32_t smem_u32(const void* p) {
    uint32_t a;
    asm("{ .reg .u64 t; cvta.to.shared.u64 t, %1; cvt.u32.u64 %0, t; }" : "=r"(a) : "l"(p));
    return a;
}
__device__ __forceinline__ void cp16(uint32_t dst, const void* src) {
    asm volatile("cp.async.cg.shared.global [%0], [%1], 16;" :: "r"(dst), "l"(src) : "memory");
}
__device__ __forceinline__ float rna_tf32(float x) {
    uint32_t u;
    asm("cvt.rna.tf32.f32 %0, %1;" : "=r"(u) : "f"(x));
    return __uint_as_float(u);
}
__device__ __forceinline__ void mma_tf32_16x8x8(float* c, const uint32_t* a, const uint32_t* b) {
    asm volatile(
        "mma.sync.aligned.m16n8k8.row.col.f32.tf32.tf32.f32 "
        "{%0,%1,%2,%3}, {%4,%5,%6,%7}, {%8,%9}, {%0,%1,%2,%3};\n"
        : "+f"(c[0]), "+f"(c[1]), "+f"(c[2]), "+f"(c[3])
        : "r"(a[0]), "r"(a[1]), "r"(a[2]), "r"(a[3]), "r"(b[0]), "r"(b[1]));
}
__device__ __forceinline__ unsigned ld_acq(unsigned* p) {
    unsigned v;
    asm volatile("ld.acquire.gpu.global.u32 %0, [%1];" : "=r"(v) : "l"(p) : "memory");
    return v;
}

// ================= tf32 mma.sync GEMM =================
// mode 0: C = A[M,K]*Bw[4096,K]^T + bias  -> g_xg[dir][m][col]   (dir = n>>11)
// mode 1: same math, N=32000              -> out[B,V,S] scatter
#define KSTR 20
#define STGF (2 * 128 * KSTR)
#define STGB (STGF * 4)
#define GEMM_DSM 67584

__global__ __launch_bounds__(128) void gemm_mma(
    const float* __restrict__ A, const float* __restrict__ Bw,
    const float* __restrict__ bias, float* __restrict__ out,
    int Kdim, int mode)
{
    extern __shared__ float dsm[];
    int tid = threadIdx.x, wid = tid >> 5, lane = tid & 31;
    int warp_m = wid & 1, warp_n = wid >> 1;
    int gr = lane >> 2, gc = lane & 3;
    int m0 = blockIdx.x << 7;
    int n0 = blockIdx.y << 7;
    uint32_t base = smem_u32(dsm);
    int KC = Kdim >> 4;

    const float* Ag = A + (size_t)m0 * Kdim;
    const float* Bg = Bw + (size_t)n0 * Kdim;

    float acc[4][8][4];
#pragma unroll
    for (int mi = 0; mi < 4; mi++)
#pragma unroll
        for (int ni = 0; ni < 8; ni++)
#pragma unroll
            for (int q = 0; q < 4; q++) acc[mi][ni][q] = 0.f;

#define LOAD_STAGE(s, c) do {                                               \
        uint32_t sb_ = base + (s) * STGB;                                   \
        const float* Ac_ = Ag + (c) * 16;                                   \
        const float* Bc_ = Bg + (c) * 16;                                   \
        _Pragma("unroll")                                                   \
        for (int q_ = 0; q_ < 4; q_++) {                                    \
            int f_ = q_ * 128 + tid;                                        \
            int row_ = f_ >> 2, k4_ = f_ & 3;                               \
            cp16(sb_ + row_ * (KSTR * 4) + k4_ * 16,                        \
                 Ac_ + (size_t)row_ * Kdim + k4_ * 4);                      \
            cp16(sb_ + 128 * (KSTR * 4) + row_ * (KSTR * 4) + k4_ * 16,    \
                 Bc_ + (size_t)row_ * Kdim + k4_ * 4);                      \
        }                                                                   \
        asm volatile("cp.async.commit_group;" ::: "memory");                \
    } while (0)

    LOAD_STAGE(0, 0);
    LOAD_STAGE(1, 1);
    LOAD_STAGE(2, 2);

    int s = 0;
    for (int c = 0; c < KC; c++) {
        asm volatile("cp.async.wait_group 2;" ::: "memory");
        __syncthreads();
        const float* As = dsm + s * STGF;
        const float* Bs = As + 128 * KSTR;
#pragma unroll
        for (int kk = 0; kk < 16; kk += 8) {
            uint32_t af[4][4], bf[8][2];
#pragma unroll
            for (int mi = 0; mi < 4; mi++) {
                int r = warp_m * 64 + mi * 16 + gr;
                const float* p = As + r * KSTR + kk + gc;
                af[mi][0] = __float_as_uint(p[0]);
                af[mi][1] = __float_as_uint(p[8 * KSTR]);
                af[mi][2] = __float_as_uint(p[4]);
                af[mi][3] = __float_as_uint(p[8 * KSTR + 4]);
            }
#pragma unroll
            for (int ni = 0; ni < 8; ni++) {
                int n = warp_n * 64 + ni * 8 + gr;
                const float* p = Bs + n * KSTR + kk + gc;
                bf[ni][0] = __float_as_uint(p[0]);
                bf[ni][1] = __float_as_uint(p[4]);
            }
#pragma unroll
            for (int mi = 0; mi < 4; mi++)
#pragma unroll
                for (int ni = 0; ni < 8; ni++)
                    mma_tf32_16x8x8(acc[mi][ni], af[mi], bf[ni]);
        }
        __syncthreads();
        if (c < KC - 3) LOAD_STAGE(s, c + 3);
        else asm volatile("cp.async.commit_group;" ::: "memory");
        s++; if (s == 3) s = 0;
    }
    asm volatile("cp.async.wait_group 0;" ::: "memory");
    __syncthreads();

    if (mode == 1) {
        // ---- transpose epilogue -> out[B,V,S] ----
        float* es = dsm;  // 128 x stride 132
#pragma unroll
        for (int mi = 0; mi < 4; mi++) {
            int row = warp_m * 64 + mi * 16 + gr;
#pragma unroll
            for (int ni = 0; ni < 8; ni++) {
                int col = warp_n * 64 + ni * 8 + gc * 2;
                es[col * 132 + row]           = acc[mi][ni][0];
                es[(col + 1) * 132 + row]     = acc[mi][ni][1];
                es[col * 132 + row + 8]       = acc[mi][ni][2];
                es[(col + 1) * 132 + row + 8] = acc[mi][ni][3];
            }
        }
        __syncthreads();
        int bb = blockIdx.x;
        float* ob = out + (size_t)bb * Vv * Ss;
#pragma unroll 4
        for (int i = 0; i < 32; i++) {
            int f4 = i * 128 + tid;
            int rown = f4 >> 5;
            int c4 = f4 & 31;
            float4 v = *reinterpret_cast<const float4*>(es + rown * 132 + c4 * 4);
            float bv = bias[n0 + rown];
            v.x += bv; v.y += bv; v.z += bv; v.w += bv;
            *reinterpret_cast<float4*>(ob + (size_t)(n0 + rown) * Ss + c4 * 4) = v;
        }
    } else {
        // ---- direct [m][col] stores into g_xg[dir] ----
        int dirq = n0 >> 11;
        float* dst = out + (size_t)dirq * ((size_t)MBr * G4);
        int ncol0 = n0 & 2047;
#pragma unroll
        for (int mi = 0; mi < 4; mi++) {
            int row = m0 + warp_m * 64 + mi * 16 + gr;
#pragma unroll
            for (int ni = 0; ni < 8; ni++) {
                int nglob = n0 + warp_n * 64 + ni * 8 + gc * 2;
                int col = ncol0 + warp_n * 64 + ni * 8 + gc * 2;
                float bv0 = bias[nglob], bv1 = bias[nglob + 1];
                float2 v0 = make_float2(acc[mi][ni][0] + bv0, acc[mi][ni][1] + bv1);
                float2 v1 = make_float2(acc[mi][ni][2] + bv0, acc[mi][ni][3] + bv1);
                *reinterpret_cast<float2*>(dst + (size_t)row * G4 + col) = v0;
                *reinterpret_cast<float2*>(dst + (size_t)(row + 8) * G4 + col) = v1;
            }
        }
    }
#undef LOAD_STAGE
}

// ---------------- rna tf32 rounding (elementwise) ----------------
__global__ void rna_round_kernel(const float* __restrict__ in, float* __restrict__ out) {
    int i = blockIdx.x * blockDim.x + threadIdx.x;
    float4 v = reinterpret_cast<const float4*>(in)[i];
    v.x = rna_tf32(v.x); v.y = rna_tf32(v.y); v.z = rna_tf32(v.z); v.w = rna_tf32(v.w);
    reinterpret_cast<float4*>(out)[i] = v;
}

// ---------------- combined bias: [f dirs 0..2047 | b dirs 2048..4095] ----------------
__global__ void bias_comb(const float* __restrict__ b1f, const float* __restrict__ b2f,
                          const float* __restrict__ b1b, const float* __restrict__ b2b) {
    int i = blockIdx.x * blockDim.x + threadIdx.x;   // 0..2047
    g_bias[i] = b1f[i] + b2f[i];
    g_bias[2048 + i] = b1b[i] + b2b[i];
}

// ---------------- embedding gather (tf32-rounded) ----------------
__global__ void embed_kernel(const int* __restrict__ tok, const float* __restrict__ ew) {
    int sb = blockIdx.x;
    int s = sb >> 4, b = sb & 15;
    int t = tok[b * Ss + s];
    float4 v = reinterpret_cast<const float4*>(ew + (size_t)t * Ee)[threadIdx.x];
    v.x = rna_tf32(v.x); v.y = rna_tf32(v.y); v.z = rna_tf32(v.z); v.w = rna_tf32(v.w);
    reinterpret_cast<float4*>(g_x0 + (size_t)sb * Ee)[threadIdx.x] = v;
}

// ================= persistent LSTM (one launch per layer) =================
// grid (64, 2): 64 unit-chunks x 2 dirs. 128 threads. All 128 blocks co-resident.
#define LSTM_DSM ((32 * 512 + 16 * 512 + 32 * 16) * 4)   // 100352 B

__global__ __launch_bounds__(128) void lstm_persist(
    const float* __restrict__ Whh_f, const float* __restrict__ Whh_b, int mode)
{
    extern __shared__ float sm[];
    float* ws = sm;                 // [32 rows][512]
    float* hs = sm + 32 * 512;      // [16 b][512]
    float* zr = hs + 16 * 512;      // [32 rows][16 b]
    int dir = blockIdx.y;
    int u0 = blockIdx.x << 3;
    int tid = threadIdx.x;
    int rg = tid >> 4, ks = tid & 15;
    int gb = tid >> 3, gu = tid & 7;
    const float* Whh = dir ? Whh_b : Whh_f;

    // stage Whh chunk once: local row lr -> gate (lr>>3), unit u0+(lr&7)
    {
        float4* d4 = reinterpret_cast<float4*>(ws);
#pragma unroll 4
        for (int i = 0; i < 32; i++) {
            int f4 = i * 128 + tid;
            int lrr = f4 >> 7, c4 = f4 & 127;
            int R = (lrr >> 3) * Hh + u0 + (lrr & 7);
            d4[f4] = *reinterpret_cast<const float4*>(Whh + (size_t)R * Hh + (c4 << 2));
        }
    }

    float creg = 0.f;
    unsigned mygen = 0;
    if (tid == 0) mygen = ld_acq(&g_bar_gen[dir]);

    for (int t = 0; t < Ss; t++) {
        int tidx = dir ? (Ss - 1 - t) : t;

        // stage h_prev
        {
            float4* h4 = reinterpret_cast<float4*>(hs);
            if (t == 0) {
                float4 z = make_float4(0.f, 0.f, 0.f, 0.f);
#pragma unroll
                for (int i = 0; i < 16; i++) h4[i * 128 + tid] = z;
            } else {
                const float4* src = reinterpret_cast<const float4*>(g_h[t & 1][dir]);
#pragma unroll
                for (int i = 0; i < 16; i++) h4[i * 128 + tid] = __ldcv(src + i * 128 + tid);
            }
        }
        __syncthreads();

        float acc[4][16];
#pragma unroll
        for (int r = 0; r < 4; r++)
#pragma unroll
            for (int b = 0; b < 16; b++) acc[r][b] = 0.f;

#pragma unroll 2
        for (int j = 0; j < 8; j++) {
            int k = (j << 6) + (ks << 2);
            const float* wr = ws + ((rg << 2) * 512) + k;
            float4 w0 = *reinterpret_cast<const float4*>(wr);
            float4 w1 = *reinterpret_cast<const float4*>(wr + 512);
            float4 w2 = *reinterpret_cast<const float4*>(wr + 1024);
            float4 w3 = *reinterpret_cast<const float4*>(wr + 1536);
#pragma unroll
            for (int b = 0; b < 16; b++) {
                float4 hv = *reinterpret_cast<const float4*>(hs + (b << 9) + k);
                acc[0][b] += w0.x * hv.x + w0.y * hv.y + w0.z * hv.z + w0.w * hv.w;
                acc[1][b] += w1.x * hv.x + w1.y * hv.y + w1.z * hv.z + w1.w * hv.w;
                acc[2][b] += w2.x * hv.x + w2.y * hv.y + w2.z * hv.z + w2.w * hv.w;
                acc[3][b] += w3.x * hv.x + w3.y * hv.y + w3.z * hv.z + w3.w * hv.w;
            }
        }

#pragma unroll
        for (int off = 8; off >= 1; off >>= 1)
#pragma unroll
            for (int r = 0; r < 4; r++)
#pragma unroll
                for (int b = 0; b < 16; b++)
                    acc[r][b] += __shfl_xor_sync(0xffffffffu, acc[r][b], off);

        if (ks == 0) {
#pragma unroll
            for (int r = 0; r < 4; r++)
#pragma unroll
                for (int b = 0; b < 16; b++)
                    zr[((rg << 2) + r) * 16 + b] = acc[r][b];
        }
        __syncthreads();

        // gates: thread <-> (b=gb, unit=u0+gu)
        {
            int unit = u0 + gu;
            const float* xgd = g_xg[dir] + (size_t)(tidx * Bb + gb) * G4 + unit;
            float zi = zr[gu * 16 + gb]        + xgd[0];
            float zf = zr[(8 + gu) * 16 + gb]  + xgd[Hh];
            float zg = zr[(16 + gu) * 16 + gb] + xgd[2 * Hh];
            float zo = zr[(24 + gu) * 16 + gb] + xgd[3 * Hh];
            float ig = 1.f / (1.f + expf(-zi));
            float fg = 1.f / (1.f + expf(-zf));
            float gg = tanhf(zg);
            float og = 1.f / (1.f + expf(-zo));
            creg = fg * creg + ig * gg;
            float h = og * tanhf(creg);
            g_h[(t & 1) ^ 1][dir][gb * Hh + unit] = h;
            if (mode == 0)
                g_x1[(size_t)(tidx * Bb + gb) * 1024 + (dir << 9) + unit] = rna_tf32(h);
            else
                g_hfin[(size_t)gb * (Ss * 1024) + tidx * 1024 + (dir << 9) + unit] = rna_tf32(h);
        }

        // per-dir grid barrier (64 blocks)
        __syncthreads();
        if (tid == 0) {
            __threadfence();
            unsigned arrived = atomicAdd(&g_bar_cnt[dir], 1u);
            mygen++;
            if (arrived == 63u) {
                g_bar_cnt[dir] = 0u;
                asm volatile("red.release.gpu.global.add.u32 [%0], 1;"
                             :: "l"(&g_bar_gen[dir]) : "memory");
            } else {
                while (ld_acq(&g_bar_gen[dir]) != mygen) { }
            }
        }
        __syncthreads();
    }
}

// ---------------- launch ----------------
extern "C" void kernel_launch(void* const* d_in, const int* in_sizes, int n_in,
                              void* d_out, int out_size)
{
    const int*   tok  = (const int*)d_in[0];
    const float* ew   = (const float*)d_in[1];
    const float* Wih0f = (const float*)d_in[2],  *Whh0f = (const float*)d_in[3];
    const float* bih0f = (const float*)d_in[4],  *bhh0f = (const float*)d_in[5];
    const float* Wih0b = (const float*)d_in[6],  *Whh0b = (const float*)d_in[7];
    const float* bih0b = (const float*)d_in[8],  *bhh0b = (const float*)d_in[9];
    const float* Wih1f = (const float*)d_in[10], *Whh1f = (const float*)d_in[11];
    const float* bih1f = (const float*)d_in[12], *bhh1f = (const float*)d_in[13];
    const float* Wih1b = (const float*)d_in[14], *Whh1b = (const float*)d_in[15];
    const float* bih1b = (const float*)d_in[16], *bhh1b = (const float*)d_in[17];
    const float* linw = (const float*)d_in[18],  *linb  = (const float*)d_in[19];
    float* out = (float*)d_out;

    float *px0, *px1, *pxg, *phf, *pwt, *pwp, *pbias;
    cudaGetSymbolAddress((void**)&px0, g_x0);
    cudaGetSymbolAddress((void**)&px1, g_x1);
    cudaGetSymbolAddress((void**)&pxg, g_xg);
    cudaGetSymbolAddress((void**)&phf, g_hfin);
    cudaGetSymbolAddress((void**)&pwt, g_wt);
    cudaGetSymbolAddress((void**)&pwp, g_wpack);
    cudaGetSymbolAddress((void**)&pbias, g_bias);   // <-- R4 bug: was passing host-shadow symbol

    cudaFuncSetAttribute(gemm_mma, cudaFuncAttributeMaxDynamicSharedMemorySize, GEMM_DSM);
    cudaFuncSetAttribute(lstm_persist, cudaFuncAttributeMaxDynamicSharedMemorySize, LSTM_DSM);

    embed_kernel<<<MBr, 128>>>(tok, ew);
    rna_round_kernel<<<(Vv * 1024 / 4) / 256, 256>>>(linw, pwt);

    // ---- layer 0 ----
    rna_round_kernel<<<(2048 * 512 / 4) / 256, 256>>>(Wih0f, pwp);
    rna_round_kernel<<<(2048 * 512 / 4) / 256, 256>>>(Wih0b, pwp + (size_t)2048 * 512);
    bias_comb<<<8, 256>>>(bih0f, bhh0f, bih0b, bhh0b);
    gemm_mma<<<dim3(16, 32), 128, GEMM_DSM>>>(px0, pwp, pbias, pxg, 512, 0);
    lstm_persist<<<dim3(64, 2), 128, LSTM_DSM>>>(Whh0f, Whh0b, 0);

    // ---- layer 1 ----
    rna_round_kernel<<<(2048 * 1024 / 4) / 256, 256>>>(Wih1f, pwp);
    rna_round_kernel<<<(2048 * 1024 / 4) / 256, 256>>>(Wih1b, pwp + (size_t)2048 * 1024);
    bias_comb<<<8, 256>>>(bih1f, bhh1f, bih1b, bhh1b);
    gemm_mma<<<dim3(16, 32), 128, GEMM_DSM>>>(px1, pwp, pbias, pxg, 1024, 0);
    lstm_persist<<<dim3(64, 2), 128, LSTM_DSM>>>(Whh1f, Whh1b, 1);

    // ---- final projection ----
    gemm_mma<<<dim3(16, 250), 128, GEMM_DSM>>>(phf, pwt, linb, out, 1024, 1);
}

// round 7
// speedup vs baseline: 2.5797x; 1.2334x over previous
#include <cuda_runtime.h>
#include <cuda_fp16.h>
#include <math.h>
#include <stdint.h>

#define Vv  32000
#define Ee  512
#define Hh  512
#define Bb  16
#define Ss  128
#define G4  2048   // 4*H
#define MBr 2048   // S*B rows

// ---------------- scratch (static device memory; no allocation) ----------------
__device__ __half g_x0h[(size_t)MBr * Ee];        // layer0 input (fp16)
__device__ __half g_x1h[(size_t)MBr * 1024];      // layer1 input (fp16)
__device__ float  g_xg[2][(size_t)MBr * G4];      // per-dir gate preacts (fp32)
__device__ float  g_h[2][2][Bb * Hh];             // [parity][dir][b*H] (fp32)
__device__ __half g_hfinh[(size_t)Bb * Ss * 1024];// layer1 output (fp16)
__device__ __half g_wth[(size_t)Vv * 1024];       // lin_w fp16
__device__ __half g_wph[(size_t)4096 * 1024];     // packed Wih fp16 (both dirs)
__device__ float  g_bias[4096];                   // combined bih+bhh (both dirs)
__device__ unsigned g_bar_cnt[2];
__device__ unsigned g_bar_gen[2];

// ================= helpers =================
__device__ __forceinline__ uint32_t smem_u32(const void* p) {
    uint32_t a;
    asm("{ .reg .u64 t; cvta.to.shared.u64 t, %1; cvt.u32.u64 %0, t; }" : "=r"(a) : "l"(p));
    return a;
}
__device__ __forceinline__ void cp16(uint32_t dst, const void* src) {
    asm volatile("cp.async.cg.shared.global [%0], [%1], 16;" :: "r"(dst), "l"(src) : "memory");
}
__device__ __forceinline__ void ldsm_x4(uint32_t* r, uint32_t addr) {
    asm volatile("ldmatrix.sync.aligned.m8n8.x4.shared.b16 {%0,%1,%2,%3}, [%4];"
                 : "=r"(r[0]), "=r"(r[1]), "=r"(r[2]), "=r"(r[3]) : "r"(addr));
}
__device__ __forceinline__ void mma_f16(float* c, const uint32_t* a, uint32_t b0, uint32_t b1) {
    asm volatile(
        "mma.sync.aligned.m16n8k16.row.col.f32.f16.f16.f32 "
        "{%0,%1,%2,%3}, {%4,%5,%6,%7}, {%8,%9}, {%0,%1,%2,%3};\n"
        : "+f"(c[0]), "+f"(c[1]), "+f"(c[2]), "+f"(c[3])
        : "r"(a[0]), "r"(a[1]), "r"(a[2]), "r"(a[3]), "r"(b0), "r"(b1));
}
__device__ __forceinline__ unsigned ld_acq(unsigned* p) {
    unsigned v;
    asm volatile("ld.acquire.gpu.global.u32 %0, [%1];" : "=r"(v) : "l"(p) : "memory");
    return v;
}

// ================= fp16 mma.sync GEMM =================
// mode 0: C = A[M,K]*Bw[4096,K]^T + bias  -> g_xg[dir][m][col]   (dir = n>>11)
// mode 1: same math, N=32000              -> out[B,V,S] scatter
// smem layout per stage: A 128 rows x 80B (32 halves + pad), B same. stage = 20480B.
#define RSTR 80                  // bytes per smem row (32 halves + 8 pad)
#define STGB (2 * 128 * RSTR)    // 20480
#define GEMM_DSM 67584           // max(3*STGB=61440, epilogue 128*132*4=67584)

__global__ __launch_bounds__(128) void gemm_mma(
    const __half* __restrict__ A, const __half* __restrict__ Bw,
    const float* __restrict__ bias, float* __restrict__ out,
    int Kdim, int mode)
{
    extern __shared__ char dsmc[];
    float* dsm = reinterpret_cast<float*>(dsmc);
    int tid = threadIdx.x, wid = tid >> 5, lane = tid & 31;
    int warp_m = wid & 1, warp_n = wid >> 1;
    int gr = lane >> 2, gc = lane & 3;
    int m0 = blockIdx.x << 7;
    int n0 = blockIdx.y << 7;
    uint32_t base = smem_u32(dsmc);
    int KC = Kdim >> 5;

    const __half* Ag = A + (size_t)m0 * Kdim;
    const __half* Bg = Bw + (size_t)n0 * Kdim;

    // per-thread ldmatrix offsets (bytes)
    uint32_t aoff = (uint32_t)((lane & 15) * RSTR + (lane >> 4) * 16)
                  + (uint32_t)(warp_m * 64 * RSTR);
    uint32_t boff = (uint32_t)(((lane & 7) + ((lane >> 3) & 1) * 8) * RSTR + (lane >> 4) * 16)
                  + (uint32_t)(warp_n * 64 * RSTR) + 128 * RSTR;

    float acc[4][8][4];
#pragma unroll
    for (int mi = 0; mi < 4; mi++)
#pragma unroll
        for (int ni = 0; ni < 8; ni++)
#pragma unroll
            for (int q = 0; q < 4; q++) acc[mi][ni][q] = 0.f;

#define LOAD_STAGE(s, c) do {                                               \
        uint32_t sb_ = base + (s) * STGB;                                   \
        const __half* Ac_ = Ag + (c) * 32;                                  \
        const __half* Bc_ = Bg + (c) * 32;                                  \
        _Pragma("unroll")                                                   \
        for (int q_ = 0; q_ < 4; q_++) {                                    \
            int f_ = q_ * 128 + tid;                                        \
            int row_ = f_ >> 2, g_ = f_ & 3;                                \
            cp16(sb_ + row_ * RSTR + g_ * 16,                               \
                 Ac_ + (size_t)row_ * Kdim + g_ * 8);                       \
            cp16(sb_ + 128 * RSTR + row_ * RSTR + g_ * 16,                  \
                 Bc_ + (size_t)row_ * Kdim + g_ * 8);                       \
        }                                                                   \
        asm volatile("cp.async.commit_group;" ::: "memory");                \
    } while (0)

    LOAD_STAGE(0, 0);
    LOAD_STAGE(1, 1);
    LOAD_STAGE(2, 2);

    int s = 0;
    for (int c = 0; c < KC; c++) {
        asm volatile("cp.async.wait_group 2;" ::: "memory");
        __syncthreads();
        uint32_t sb = base + s * STGB;
#pragma unroll
        for (int kb = 0; kb < 64; kb += 32) {   // two k16 sub-steps (32 bytes each)
            uint32_t af[4][4], bf[4][4];
#pragma unroll
            for (int mi = 0; mi < 4; mi++)
                ldsm_x4(af[mi], sb + aoff + (uint32_t)(mi * 16 * RSTR) + kb);
#pragma unroll
            for (int nj = 0; nj < 4; nj++)
                ldsm_x4(bf[nj], sb + boff + (uint32_t)(nj * 16 * RSTR) + kb);
#pragma unroll
            for (int mi = 0; mi < 4; mi++)
#pragma unroll
                for (int ni = 0; ni < 8; ni++)
                    mma_f16(acc[mi][ni], af[mi],
                            bf[ni >> 1][ni & 1], bf[ni >> 1][2 + (ni & 1)]);
        }
        __syncthreads();
        if (c < KC - 3) LOAD_STAGE(s, c + 3);
        else asm volatile("cp.async.commit_group;" ::: "memory");
        s++; if (s == 3) s = 0;
    }
    asm volatile("cp.async.wait_group 0;" ::: "memory");
    __syncthreads();

    if (mode == 1) {
        // ---- transpose epilogue -> out[B,V,S] ----
        float* es = dsm;  // 128 x stride 132
#pragma unroll
        for (int mi = 0; mi < 4; mi++) {
            int row = warp_m * 64 + mi * 16 + gr;
#pragma unroll
            for (int ni = 0; ni < 8; ni++) {
                int col = warp_n * 64 + ni * 8 + gc * 2;
                es[col * 132 + row]           = acc[mi][ni][0];
                es[(col + 1) * 132 + row]     = acc[mi][ni][1];
                es[col * 132 + row + 8]       = acc[mi][ni][2];
                es[(col + 1) * 132 + row + 8] = acc[mi][ni][3];
            }
        }
        __syncthreads();
        int bb = blockIdx.x;
        float* ob = out + (size_t)bb * Vv * Ss;
#pragma unroll 4
        for (int i = 0; i < 32; i++) {
            int f4 = i * 128 + tid;
            int rown = f4 >> 5;
            int c4 = f4 & 31;
            float4 v = *reinterpret_cast<const float4*>(es + rown * 132 + c4 * 4);
            float bv = bias[n0 + rown];
            v.x += bv; v.y += bv; v.z += bv; v.w += bv;
            *reinterpret_cast<float4*>(ob + (size_t)(n0 + rown) * Ss + c4 * 4) = v;
        }
    } else {
        // ---- direct [m][col] stores into g_xg[dir] ----
        int dirq = n0 >> 11;
        float* dst = out + (size_t)dirq * ((size_t)MBr * G4);
        int ncol0 = n0 & 2047;
#pragma unroll
        for (int mi = 0; mi < 4; mi++) {
            int row = m0 + warp_m * 64 + mi * 16 + gr;
#pragma unroll
            for (int ni = 0; ni < 8; ni++) {
                int nglob = n0 + warp_n * 64 + ni * 8 + gc * 2;
                int col = ncol0 + warp_n * 64 + ni * 8 + gc * 2;
                float bv0 = bias[nglob], bv1 = bias[nglob + 1];
                float2 v0 = make_float2(acc[mi][ni][0] + bv0, acc[mi][ni][1] + bv1);
                float2 v1 = make_float2(acc[mi][ni][2] + bv0, acc[mi][ni][3] + bv1);
                *reinterpret_cast<float2*>(dst + (size_t)row * G4 + col) = v0;
                *reinterpret_cast<float2*>(dst + (size_t)(row + 8) * G4 + col) = v1;
            }
        }
    }
#undef LOAD_STAGE
}

// ---------------- fp32 -> fp16 conversion (vectorized) ----------------
__global__ void cvt_half_kernel(const float* __restrict__ in, __half* __restrict__ out) {
    int i = blockIdx.x * blockDim.x + threadIdx.x;
    float4 v = reinterpret_cast<const float4*>(in)[i];
    __half2 h0 = __floats2half2_rn(v.x, v.y);
    __half2 h1 = __floats2half2_rn(v.z, v.w);
    reinterpret_cast<__half2*>(out)[2 * i]     = h0;
    reinterpret_cast<__half2*>(out)[2 * i + 1] = h1;
}

// ---------------- combined bias: [f dirs 0..2047 | b dirs 2048..4095] ----------------
__global__ void bias_comb(const float* __restrict__ b1f, const float* __restrict__ b2f,
                          const float* __restrict__ b1b, const float* __restrict__ b2b) {
    int i = blockIdx.x * blockDim.x + threadIdx.x;   // 0..2047
    g_bias[i] = b1f[i] + b2f[i];
    g_bias[2048 + i] = b1b[i] + b2b[i];
}

// ---------------- embedding gather (fp16 out) ----------------
__global__ void embed_kernel(const int* __restrict__ tok, const float* __restrict__ ew) {
    int sb = blockIdx.x;
    int s = sb >> 4, b = sb & 15;
    int t = tok[b * Ss + s];
    float4 v = reinterpret_cast<const float4*>(ew + (size_t)t * Ee)[threadIdx.x];
    __half2* dst = reinterpret_cast<__half2*>(g_x0h + (size_t)sb * Ee);
    dst[2 * threadIdx.x]     = __floats2half2_rn(v.x, v.y);
    dst[2 * threadIdx.x + 1] = __floats2half2_rn(v.z, v.w);
}

// ================= persistent LSTM (one launch per layer) =================
// grid (64, 2): 64 unit-chunks x 2 dirs. 128 threads. All 128 blocks co-resident.
#define LSTM_DSM ((32 * 512 + 16 * 512 + 32 * 16) * 4)   // 100352 B

__global__ __launch_bounds__(128) void lstm_persist(
    const float* __restrict__ Whh_f, const float* __restrict__ Whh_b, int mode)
{
    extern __shared__ float sm[];
    float* ws = sm;                 // [32 rows][512]
    float* hs = sm + 32 * 512;      // [16 b][512]
    float* zr = hs + 16 * 512;      // [32 rows][16 b]
    int dir = blockIdx.y;
    int u0 = blockIdx.x << 3;
    int tid = threadIdx.x;
    int rg = tid >> 4, ks = tid & 15;
    int gb = tid >> 3, gu = tid & 7;
    const float* Whh = dir ? Whh_b : Whh_f;

    {
        float4* d4 = reinterpret_cast<float4*>(ws);
#pragma unroll 4
        for (int i = 0; i < 32; i++) {
            int f4 = i * 128 + tid;
            int lrr = f4 >> 7, c4 = f4 & 127;
            int R = (lrr >> 3) * Hh + u0 + (lrr & 7);
            d4[f4] = *reinterpret_cast<const float4*>(Whh + (size_t)R * Hh + (c4 << 2));
        }
    }

    float creg = 0.f;
    unsigned mygen = 0;
    if (tid == 0) mygen = ld_acq(&g_bar_gen[dir]);

    for (int t = 0; t < Ss; t++) {
        int tidx = dir ? (Ss - 1 - t) : t;

        {
            float4* h4 = reinterpret_cast<float4*>(hs);
            if (t == 0) {
                float4 z = make_float4(0.f, 0.f, 0.f, 0.f);
#pragma unroll
                for (int i = 0; i < 16; i++) h4[i * 128 + tid] = z;
            } else {
                const float4* src = reinterpret_cast<const float4*>(g_h[t & 1][dir]);
#pragma unroll
                for (int i = 0; i < 16; i++) h4[i * 128 + tid] = __ldcv(src + i * 128 + tid);
            }
        }
        __syncthreads();

        float acc[4][16];
#pragma unroll
        for (int r = 0; r < 4; r++)
#pragma unroll
            for (int b = 0; b < 16; b++) acc[r][b] = 0.f;

#pragma unroll 2
        for (int j = 0; j < 8; j++) {
            int k = (j << 6) + (ks << 2);
            const float* wr = ws + ((rg << 2) * 512) + k;
            float4 w0 = *reinterpret_cast<const float4*>(wr);
            float4 w1 = *reinterpret_cast<const float4*>(wr + 512);
            float4 w2 = *reinterpret_cast<const float4*>(wr + 1024);
            float4 w3 = *reinterpret_cast<const float4*>(wr + 1536);
#pragma unroll
            for (int b = 0; b < 16; b++) {
                float4 hv = *reinterpret_cast<const float4*>(hs + (b << 9) + k);
                acc[0][b] += w0.x * hv.x + w0.y * hv.y + w0.z * hv.z + w0.w * hv.w;
                acc[1][b] += w1.x * hv.x + w1.y * hv.y + w1.z * hv.z + w1.w * hv.w;
                acc[2][b] += w2.x * hv.x + w2.y * hv.y + w2.z * hv.z + w2.w * hv.w;
                acc[3][b] += w3.x * hv.x + w3.y * hv.y + w3.z * hv.z + w3.w * hv.w;
            }
        }

#pragma unroll
        for (int off = 8; off >= 1; off >>= 1)
#pragma unroll
            for (int r = 0; r < 4; r++)
#pragma unroll
                for (int b = 0; b < 16; b++)
                    acc[r][b] += __shfl_xor_sync(0xffffffffu, acc[r][b], off);

        if (ks == 0) {
#pragma unroll
            for (int r = 0; r < 4; r++)
#pragma unroll
                for (int b = 0; b < 16; b++)
                    zr[((rg << 2) + r) * 16 + b] = acc[r][b];
        }
        __syncthreads();

        {
            int unit = u0 + gu;
            const float* xgd = g_xg[dir] + (size_t)(tidx * Bb + gb) * G4 + unit;
            float zi = zr[gu * 16 + gb]        + xgd[0];
            float zf = zr[(8 + gu) * 16 + gb]  + xgd[Hh];
            float zg = zr[(16 + gu) * 16 + gb] + xgd[2 * Hh];
            float zo = zr[(24 + gu) * 16 + gb] + xgd[3 * Hh];
            float ig = 1.f / (1.f + expf(-zi));
            float fg = 1.f / (1.f + expf(-zf));
            float gg = tanhf(zg);
            float og = 1.f / (1.f + expf(-zo));
            creg = fg * creg + ig * gg;
            float h = og * tanhf(creg);
            g_h[(t & 1) ^ 1][dir][gb * Hh + unit] = h;
            if (mode == 0)
                g_x1h[(size_t)(tidx * Bb + gb) * 1024 + (dir << 9) + unit] = __float2half_rn(h);
            else
                g_hfinh[(size_t)gb * (Ss * 1024) + tidx * 1024 + (dir << 9) + unit] = __float2half_rn(h);
        }

        __syncthreads();
        if (tid == 0) {
            __threadfence();
            unsigned arrived = atomicAdd(&g_bar_cnt[dir], 1u);
            mygen++;
            if (arrived == 63u) {
                g_bar_cnt[dir] = 0u;
                asm volatile("red.release.gpu.global.add.u32 [%0], 1;"
                             :: "l"(&g_bar_gen[dir]) : "memory");
            } else {
                while (ld_acq(&g_bar_gen[dir]) != mygen) { }
            }
        }
        __syncthreads();
    }
}

// ---------------- launch ----------------
extern "C" void kernel_launch(void* const* d_in, const int* in_sizes, int n_in,
                              void* d_out, int out_size)
{
    const int*   tok  = (const int*)d_in[0];
    const float* ew   = (const float*)d_in[1];
    const float* Wih0f = (const float*)d_in[2],  *Whh0f = (const float*)d_in[3];
    const float* bih0f = (const float*)d_in[4],  *bhh0f = (const float*)d_in[5];
    const float* Wih0b = (const float*)d_in[6],  *Whh0b = (const float*)d_in[7];
    const float* bih0b = (const float*)d_in[8],  *bhh0b = (const float*)d_in[9];
    const float* Wih1f = (const float*)d_in[10], *Whh1f = (const float*)d_in[11];
    const float* bih1f = (const float*)d_in[12], *bhh1f = (const float*)d_in[13];
    const float* Wih1b = (const float*)d_in[14], *Whh1b = (const float*)d_in[15];
    const float* bih1b = (const float*)d_in[16], *bhh1b = (const float*)d_in[17];
    const float* linw = (const float*)d_in[18],  *linb  = (const float*)d_in[19];
    float* out = (float*)d_out;

    __half *px0, *px1, *phf, *pwt, *pwp;
    float *pxg, *pbias;
    cudaGetSymbolAddress((void**)&px0, g_x0h);
    cudaGetSymbolAddress((void**)&px1, g_x1h);
    cudaGetSymbolAddress((void**)&pxg, g_xg);
    cudaGetSymbolAddress((void**)&phf, g_hfinh);
    cudaGetSymbolAddress((void**)&pwt, g_wth);
    cudaGetSymbolAddress((void**)&pwp, g_wph);
    cudaGetSymbolAddress((void**)&pbias, g_bias);

    cudaFuncSetAttribute(gemm_mma, cudaFuncAttributeMaxDynamicSharedMemorySize, GEMM_DSM);
    cudaFuncSetAttribute(lstm_persist, cudaFuncAttributeMaxDynamicSharedMemorySize, LSTM_DSM);

    embed_kernel<<<MBr, 128>>>(tok, ew);
    cvt_half_kernel<<<(Vv * 1024 / 4) / 256, 256>>>(linw, pwt);

    // ---- layer 0 ----
    cvt_half_kernel<<<(2048 * 512 / 4) / 256, 256>>>(Wih0f, pwp);
    cvt_half_kernel<<<(2048 * 512 / 4) / 256, 256>>>(Wih0b, pwp + (size_t)2048 * 512);
    bias_comb<<<8, 256>>>(bih0f, bhh0f, bih0b, bhh0b);
    gemm_mma<<<dim3(16, 32), 128, GEMM_DSM>>>(px0, pwp, pbias, pxg, 512, 0);
    lstm_persist<<<dim3(64, 2), 128, LSTM_DSM>>>(Whh0f, Whh0b, 0);

    // ---- layer 1 ----
    cvt_half_kernel<<<(2048 * 1024 / 4) / 256, 256>>>(Wih1f, pwp);
    cvt_half_kernel<<<(2048 * 1024 / 4) / 256, 256>>>(Wih1b, pwp + (size_t)2048 * 1024);
    bias_comb<<<8, 256>>>(bih1f, bhh1f, bih1b, bhh1b);
    gemm_mma<<<dim3(16, 32), 128, GEMM_DSM>>>(px1, pwp, pbias, pxg, 1024, 0);
    lstm_persist<<<dim3(64, 2), 128, LSTM_DSM>>>(Whh1f, Whh1b, 1);

    // ---- final projection ----
    gemm_mma<<<dim3(16, 250), 128, GEMM_DSM>>>(phf, pwt, linb, out, 1024, 1);
}